// round 7
// baseline (speedup 1.0000x reference)
#include <cuda_runtime.h>

#define HH 1024
#define WW 1024
#define NPIX (HH * WW)

// Persistent device-global scratch (no cudaMalloc allowed).
__device__ float4 g_P[NPIX];    // row-normalized 4-neighbor weights; all-zero at seeds
__device__ float2 g_buf[NPIX];  // ping-pong partner of d_out

__global__ __launch_bounds__(256)
void rw_setup_kernel(const float* __restrict__ img,
                     const int* __restrict__ seeds,
                     float2* __restrict__ x0)
{
    int j = blockIdx.x * 32 + threadIdx.x;
    int i = blockIdx.y * blockDim.y + threadIdx.y;
    int idx = i * WW + j;

    float c  = img[idx];
    bool  cb = (c > 0.1f);

    const int di[4] = {-1, 1, 0, 0};
    const int dj[4] = { 0, 0,-1, 1};

    float w[4];
    float rowsum = 0.0f;
#pragma unroll
    for (int d = 0; d < 4; d++) {
        int ni = i + di[d], nj = j + dj[d];
        bool valid = (ni >= 0) && (ni < HH) && (nj >= 0) && (nj < WW);
        int nidx = (valid ? ni : i) * WW + (valid ? nj : j);
        float nb = img[nidx];
        float same = ((nb > 0.1f) != cb) ? 1.0f : 0.0f;
        float diff = c - nb + same;
        float wt = valid ? expf(-1.0f - fabsf(diff)) : 0.0f;
        w[d] = wt;
        rowsum += wt;
    }
    float inv = 1.0f / rowsum;

    int s = seeds[idx];
    // Seed rows are absorbing: all-zero weights -> self coefficient = 1 exactly.
    float4 p = s ? make_float4(0.f, 0.f, 0.f, 0.f)
                 : make_float4(w[0] * inv, w[1] * inv, w[2] * inv, w[3] * inv);
    g_P[idx] = p;

    float2 x;
    x.x = (s == 1) ? 1.0f : 0.0f;
    x.y = (s == 2) ? 1.0f : 0.0f;
    x0[idx] = x;
}

// ---------------------------------------------------------------------------
// Four Jacobi steps per launch; x/y ping-pong in smem; P from L2-resident
// global. Incremental indexing (no div/mod in loops), interior/boundary
// specialization, 7 blocks/SM single wave.
// ---------------------------------------------------------------------------
#define TX 32
#define TY 32
#define AW 40
#define BW 38

// One Jacobi sub-step over a DxD region. Incremental addressing.
//  D:     output region side        IW/CI:  input stride / center offset
//  OW/OO: output stride / offset    PR:     region radius (global origin by-PR)
//  GUARD: P loads may be out of image
template<int D, int IW, int CI, int OW, int OO, int PR, bool GUARD>
__device__ __forceinline__
void rw_phase(int tid, int by, int bx,
              const float2* __restrict__ sin_, float2* __restrict__ sout)
{
    constexpr int NITER = (D * D + 255) / 256;
    constexpr int DR    = 256 / D;
    constexpr int DC    = 256 % D;
    constexpr bool EXACT = (NITER * 256 == D * D);
    // pointer deltas (elements), wrap vs no-wrap
    constexpr int DIN_N = DR * IW + DC,       DIN_W = (DR + 1) * IW + DC - D;
    constexpr int DOU_N = DR * OW + DC,       DOU_W = (DR + 1) * OW + DC - D;
    constexpr int DPG_N = DR * WW + DC,       DPG_W = (DR + 1) * WW + DC - D;

    int r = tid / D;
    int c = tid - r * D;
    const float2* ip = sin_ + (r + CI) * IW + (c + CI);
    float2*       op = sout + (r + OO) * OW + (c + OO);
    const float4* pp = g_P + (by - PR + r) * WW + (bx - PR + c);
    int e = tid;

#pragma unroll 2
    for (int it = 0; it < NITER; it++) {
        if (EXACT || e < D * D) {
            float4 p;
            if (GUARD) {
                int gy = by - PR + r, gx = bx - PR + c;
                if ((unsigned)gy < HH && (unsigned)gx < WW) p = *pp;
                else p = make_float4(0.f, 0.f, 0.f, 0.f);
            } else {
                p = *pp;
            }
            float2 up = ip[-IW];
            float2 dn = ip[ IW];
            float2 lf = ip[ -1];
            float2 rt = ip[  1];
            float2 ct = ip[  0];
            float self = 1.0f - ((p.x + p.y) + (p.z + p.w));
            float2 o;
            o.x = p.x * up.x + p.y * dn.x + p.z * lf.x + p.w * rt.x + self * ct.x;
            o.y = p.x * up.y + p.y * dn.y + p.z * lf.y + p.w * rt.y + self * ct.y;
            *op = o;
        }
        if (it + 1 < NITER) {
            c += DC;
            bool wrap = (c >= D);
            if (wrap) c -= D;
            r += wrap ? (DR + 1) : DR;
            e += 256;
            ip += wrap ? DIN_W : DIN_N;
            op += wrap ? DOU_W : DOU_N;
            pp += wrap ? DPG_W : DPG_N;
        }
    }
}

template<bool GUARD>
__device__ __forceinline__
void rw_body(int tid, int by, int bx,
             const float2* __restrict__ xin, float2* __restrict__ xout,
             float2* __restrict__ sA, float2* __restrict__ sB)
{
    // ---- load x with radius-4 halo into sA (40x40) ----
    {
        constexpr int D = AW;                 // 40
        constexpr int DR = 256 / D;           // 6
        constexpr int DC = 256 % D;           // 16
        int r = tid / D;
        int c = tid - r * D;
        const float2* gp = xin + (by - 4 + r) * WW + (bx - 4 + c);
        float2*       sp = sA + r * D + c;
        int e = tid;
#pragma unroll 2
        for (int it = 0; it < 7; it++) {
            if (e < D * D) {
                float2 v;
                if (GUARD) {
                    int gy = by - 4 + r, gx = bx - 4 + c;
                    if ((unsigned)gy < HH && (unsigned)gx < WW) v = *gp;
                    else v = make_float2(0.f, 0.f);
                } else {
                    v = *gp;
                }
                *sp = v;
            }
            c += DC;
            bool wrap = (c >= D);
            if (wrap) c -= D;
            r += wrap ? (DR + 1) : DR;
            e += 256;
            gp += wrap ? ((DR + 1) * WW + DC - D) : (DR * WW + DC);
            sp += wrap ? ((DR + 1) * D  + DC - D) : (DR * D  + DC);
        }
    }
    __syncthreads();

    rw_phase<38, AW, 1, BW, 0, 3, GUARD>(tid, by, bx, sA, sB);
    __syncthreads();
    rw_phase<36, BW, 1, AW, 2, 2, GUARD>(tid, by, bx, sB, sA);
    __syncthreads();
    rw_phase<34, AW, 3, BW, 2, 1, GUARD>(tid, by, bx, sA, sB);
    __syncthreads();
    // final step writes straight to global; tile always in-bounds -> no guard
    rw_phase<32, BW, 3, WW, 0, 0, false>(tid, by, bx, sB, xout + by * WW + bx);
}

__global__ __launch_bounds__(256, 7)
void rw_step4_kernel(const float2* __restrict__ xin,
                     float2* __restrict__ xout)
{
    __shared__ float2 sA[AW * AW];  // 12.8 KB
    __shared__ float2 sB[BW * BW];  // 11.5 KB

    const int tid = threadIdx.x;
    const int bx  = blockIdx.x * TX;
    const int by  = blockIdx.y * TY;

    const bool interior = (bx >= 4) && (bx + TX + 4 <= WW) &&
                          (by >= 4) && (by + TY + 4 <= HH);
    if (interior) rw_body<false>(tid, by, bx, xin, xout, sA, sB);
    else          rw_body<true >(tid, by, bx, xin, xout, sA, sB);
}

extern "C" void kernel_launch(void* const* d_in, const int* in_sizes, int n_in,
                              void* d_out, int out_size)
{
    const float* img   = (const float*)d_in[0];
    const int*   seeds = (const int*)d_in[1];
    float2*      A     = (float2*)d_out;

    float2* B = nullptr;
    cudaGetSymbolAddress((void**)&B, g_buf);

    {
        dim3 blk(32, 8);
        dim3 grd(WW / 32, HH / 8);
        // x0 written into B; 25 quad-step kernels alternate B->A->B...,
        // t=24 (even) writes A = d_out.
        rw_setup_kernel<<<grd, blk>>>(img, seeds, B);
    }

    dim3 blk(256);
    dim3 grd(WW / TX, HH / TY);
    for (int t = 0; t < 25; t++) {
        const float2* xin  = (t & 1) ? A : B;
        float2*       xout = (t & 1) ? B : A;
        rw_step4_kernel<<<grd, blk>>>(xin, xout);
    }
}

// round 8
// speedup vs baseline: 1.2352x; 1.2352x over previous
#include <cuda_runtime.h>

#define HH 1024
#define WW 1024
#define NPIX (HH * WW)

// Persistent device-global scratch (no cudaMalloc allowed).
__device__ float4 g_P[NPIX];    // row-normalized 4-neighbor weights; all-zero at seeds
__device__ float2 g_buf[NPIX];  // ping-pong partner of d_out

__global__ __launch_bounds__(256)
void rw_setup_kernel(const float* __restrict__ img,
                     const int* __restrict__ seeds,
                     float2* __restrict__ x0)
{
    int j = blockIdx.x * 32 + threadIdx.x;
    int i = blockIdx.y * blockDim.y + threadIdx.y;
    int idx = i * WW + j;

    float c  = img[idx];
    bool  cb = (c > 0.1f);

    const int di[4] = {-1, 1, 0, 0};
    const int dj[4] = { 0, 0,-1, 1};

    float w[4];
    float rowsum = 0.0f;
#pragma unroll
    for (int d = 0; d < 4; d++) {
        int ni = i + di[d], nj = j + dj[d];
        bool valid = (ni >= 0) && (ni < HH) && (nj >= 0) && (nj < WW);
        int nidx = (valid ? ni : i) * WW + (valid ? nj : j);
        float nb = img[nidx];
        float same = ((nb > 0.1f) != cb) ? 1.0f : 0.0f;
        float diff = c - nb + same;
        float wt = valid ? expf(-1.0f - fabsf(diff)) : 0.0f;
        w[d] = wt;
        rowsum += wt;
    }
    float inv = 1.0f / rowsum;

    int s = seeds[idx];
    // Seed rows are absorbing: all-zero weights -> self coefficient = 1 exactly.
    float4 p = s ? make_float4(0.f, 0.f, 0.f, 0.f)
                 : make_float4(w[0] * inv, w[1] * inv, w[2] * inv, w[3] * inv);
    g_P[idx] = p;

    float2 x;
    x.x = (s == 1) ? 1.0f : 0.0f;
    x.y = (s == 2) ? 1.0f : 0.0f;
    x0[idx] = x;
}

// ---------------------------------------------------------------------------
// Four Jacobi steps per launch. Vertical-pair threads (2 px/thread, shared
// 4-row center column -> 8 LDS per 2 px). Phase 0 reads x straight from
// global (no staging). P from L2 with 2 batched loads per pair.
//   sA: 38x38 logical origin (by-3, bx-3)   sB: 36x36 origin (by-2, bx-2)
//   p0: global->sA (R=3)  p1: sA->sB (R=2)  p2: sB->sA (R=1)  p3: sA->global
// ---------------------------------------------------------------------------
#define TX 32
#define TY 32
#define SA 38
#define SB 36

// One Jacobi sub-step over a DxD output region, 2 vertically-adjacent px per
// thread. in_log/out_log point at logical pixel (by, bx) of their buffers.
//  D:  region side (even)   R: region radius (logical rows/cols in [-R, D-R))
//  SI/SO: input/output strides   GUARD: coords may leave the image
//  GIN: input is global memory (x reads guarded when GUARD)
template<int D, int R, int SI, int SO, bool GUARD, bool GIN>
__device__ __forceinline__
void pair_phase(int tid, int by, int bx,
                const float2* __restrict__ in_log,
                float2* __restrict__ out_log)
{
    constexpr int TOT   = D * (D / 2);
    constexpr int NITER = (TOT + 255) / 256;
    constexpr bool EXACT = (NITER * 256 == TOT);

    for (int it = 0; it < NITER; it++) {
        int e = tid + it * 256;
        if (EXACT || e < TOT) {
            int pr = e / D;
            int cc = e - pr * D;
            int ro = 2 * pr - R;   // logical row of first output px
            int co = cc - R;       // logical col

            // --- P loads first (deep MLP; L2-resident) ---
            const float4* pp = g_P + (by + ro) * WW + (bx + co);
            float4 p1, p2;
            if (GUARD) {
                bool vc = (unsigned)(bx + co) < WW;
                p1 = (vc && (unsigned)(by + ro)     < HH) ? pp[0]  : make_float4(0.f,0.f,0.f,0.f);
                p2 = (vc && (unsigned)(by + ro + 1) < HH) ? pp[WW] : make_float4(0.f,0.f,0.f,0.f);
            } else {
                p1 = pp[0];
                p2 = pp[WW];
            }

            // --- x reads: 4-row center column + lf/rt for both rows ---
            const float2* ip = in_log + ro * SI + co;
            float2 a, b, c, d, lf0, rt0, lf1, rt1;
            if (GIN && GUARD) {
                bool vc  = (unsigned)(bx + co)     < WW;
                bool vcl = (unsigned)(bx + co - 1) < WW;
                bool vcr = (unsigned)(bx + co + 1) < WW;
                bool vym = (unsigned)(by + ro - 1) < HH;
                bool vy0 = (unsigned)(by + ro)     < HH;
                bool vy1 = (unsigned)(by + ro + 1) < HH;
                bool vy2 = (unsigned)(by + ro + 2) < HH;
                const float2 z = make_float2(0.f, 0.f);
                a   = (vym && vc ) ? ip[-SI]     : z;
                b   = (vy0 && vc ) ? ip[0]       : z;
                c   = (vy1 && vc ) ? ip[SI]      : z;
                d   = (vy2 && vc ) ? ip[2 * SI]  : z;
                lf0 = (vy0 && vcl) ? ip[-1]      : z;
                rt0 = (vy0 && vcr) ? ip[1]       : z;
                lf1 = (vy1 && vcl) ? ip[SI - 1]  : z;
                rt1 = (vy1 && vcr) ? ip[SI + 1]  : z;
            } else {
                a   = ip[-SI];
                b   = ip[0];
                c   = ip[SI];
                d   = ip[2 * SI];
                lf0 = ip[-1];
                rt0 = ip[1];
                lf1 = ip[SI - 1];
                rt1 = ip[SI + 1];
            }

            float s1 = 1.0f - ((p1.x + p1.y) + (p1.z + p1.w));
            float s2 = 1.0f - ((p2.x + p2.y) + (p2.z + p2.w));
            float2 o0, o1;
            o0.x = p1.x*a.x + p1.y*c.x + p1.z*lf0.x + p1.w*rt0.x + s1*b.x;
            o0.y = p1.x*a.y + p1.y*c.y + p1.z*lf0.y + p1.w*rt0.y + s1*b.y;
            o1.x = p2.x*b.x + p2.y*d.x + p2.z*lf1.x + p2.w*rt1.x + s2*c.x;
            o1.y = p2.x*b.y + p2.y*d.y + p2.z*lf1.y + p2.w*rt1.y + s2*c.y;

            out_log[ro * SO + co]       = o0;
            out_log[(ro + 1) * SO + co] = o1;
        }
    }
}

template<bool GUARD>
__device__ __forceinline__
void rw_body(int tid, int by, int bx,
             const float2* __restrict__ xin, float2* __restrict__ xout,
             float2* __restrict__ sAl, float2* __restrict__ sBl)
{
    const float2* gin  = xin  + by * WW + bx;
    float2*       gout = xout + by * WW + bx;

    pair_phase<38, 3, WW, SA, GUARD, true >(tid, by, bx, gin, sAl);   // global -> sA
    __syncthreads();
    pair_phase<36, 2, SA, SB, GUARD, false>(tid, by, bx, sAl, sBl);   // sA -> sB
    __syncthreads();
    pair_phase<34, 1, SB, SA, GUARD, false>(tid, by, bx, sBl, sAl);   // sB -> sA
    __syncthreads();
    // final tile is fully in-image -> never guarded
    pair_phase<32, 0, SA, WW, false, false>(tid, by, bx, sAl, gout);  // sA -> global
}

__global__ __launch_bounds__(256, 7)
void rw_step4_kernel(const float2* __restrict__ xin,
                     float2* __restrict__ xout)
{
    __shared__ float2 sA[SA * SA];  // 11.55 KB
    __shared__ float2 sB[SB * SB];  // 10.4 KB

    const int tid = threadIdx.x;
    const int bx  = blockIdx.x * TX;
    const int by  = blockIdx.y * TY;

    float2* sAl = sA + 3 * SA + 3;  // logical (by, bx)
    float2* sBl = sB + 2 * SB + 2;

    const bool interior = (bx >= 4) && (bx + 36 <= WW) &&
                          (by >= 4) && (by + 36 <= HH);
    if (interior) rw_body<false>(tid, by, bx, xin, xout, sAl, sBl);
    else          rw_body<true >(tid, by, bx, xin, xout, sAl, sBl);
}

extern "C" void kernel_launch(void* const* d_in, const int* in_sizes, int n_in,
                              void* d_out, int out_size)
{
    const float* img   = (const float*)d_in[0];
    const int*   seeds = (const int*)d_in[1];
    float2*      A     = (float2*)d_out;

    float2* B = nullptr;
    cudaGetSymbolAddress((void**)&B, g_buf);

    {
        dim3 blk(32, 8);
        dim3 grd(WW / 32, HH / 8);
        // x0 written into B; 25 quad-step kernels alternate B->A->B...,
        // t=24 (even) writes A = d_out.
        rw_setup_kernel<<<grd, blk>>>(img, seeds, B);
    }

    dim3 blk(256);
    dim3 grd(WW / TX, HH / TY);
    for (int t = 0; t < 25; t++) {
        const float2* xin  = (t & 1) ? A : B;
        float2*       xout = (t & 1) ? B : A;
        rw_step4_kernel<<<grd, blk>>>(xin, xout);
    }
}